// round 10
// baseline (speedup 1.0000x reference)
#include <cuda_runtime.h>

#define BB   1024
#define FF   39
#define KK   16
#define PP   741
#define PPP  768                      // padded pair stride
#define TT   9139
#define TTP  9216                     // padded triple stride
#define SE   20                       // embedding row stride (floats)
#define NTHR 256
#define RB   4                        // batch rows per CTA in fused passes
#define NBG  (BB / RB)                // 256 batch groups
#define GSP  8                        // g-split in reduce kernel

// ---- device-global scratch (no allocations allowed) ----
__device__ float g_PS3[(size_t)NBG * TTP];   // 9.4 MB  per-bgroup sum partials
__device__ float g_PQ3[(size_t)NBG * TTP];   // 9.4 MB  per-bgroup sumsq partials
__device__ float g_PS2[NBG * PPP];           // 0.8 MB
__device__ float g_PQ2[NBG * PPP];           // 0.8 MB
__device__ float g_s2[PPP], g_q2[PPP];
__device__ float g_s3[TTP], g_q3[TTP];
__device__ __align__(16) float g_c2[PPP];
__device__ __align__(16) float g_c3[TTP];
__device__ int   g_qdec[PP];                 // a | (b2<<8), canonical pair order
__device__ float g_g2[PP], g_b2p[PP], g_w2[PP];   // BN params permuted to canonical
__device__ float g_g3[TT], g_b3p[TT], g_w3[TT];
__device__ float g_sumo;

// ---------------------------------------------------------------------------
// Kernel 0: canonical orderings + permuted BN params; zero atomic targets
//   pair  (a,b2):   q  = b2(b2-1)/2 + a      (b2-major)
//   triple(a,b2,c): tc = C(c,3) + q
// ---------------------------------------------------------------------------
__global__ void pack_tri(const int* __restrict__ i1, const int* __restrict__ i2,
                         const int* __restrict__ i3,
                         const int* __restrict__ rows, const int* __restrict__ cols,
                         const float* __restrict__ gamma2, const float* __restrict__ beta2,
                         const float* __restrict__ gw2,
                         const float* __restrict__ gamma3, const float* __restrict__ beta3,
                         const float* __restrict__ gw3) {
    int t = blockIdx.x * blockDim.x + threadIdx.x;
    if (t < TT) {
        int a = i1[t], b2 = i2[t], c = i3[t];
        int tc = (c * (c - 1) * (c - 2)) / 6 + (b2 * (b2 - 1)) / 2 + a;
        g_g3[tc]  = gamma3[t];
        g_b3p[tc] = beta3[t];
        g_w3[tc]  = gw3[t];
    }
    if (t < PP) {
        int r = rows[t], cl = cols[t];            // r > cl
        int q = (r * (r - 1)) / 2 + cl;
        g_qdec[q] = cl | (r << 8);
        g_g2[q]  = gamma2[t];
        g_b2p[q] = beta2[t];
        g_w2[q]  = gw2[t];
    }
    if (t < TTP) { g_s3[t] = 0.f; g_q3[t] = 0.f; }
    if (t < PPP) { g_s2[t] = 0.f; g_q2[t] = 0.f; }
    if (t == 0)  g_sumo = 0.f;
}

// ---------------------------------------------------------------------------
// Pass S: recompute L3/L2 values for RB rows; write per-bgroup s/q partials
// (reduction over rows in registers; one non-atomic store pair per column)
// ---------------------------------------------------------------------------
__global__ __launch_bounds__(NTHR, 2) void pass_stats(
    const int* __restrict__ feats, const float* __restrict__ v)
{
    __shared__ float st[RB * FF * SE];   // 12.5 KB: RB embedding tiles
    __shared__ int   sidx[RB * FF];

    const int bg  = blockIdx.x;
    const int b0  = bg * RB;
    const int tid = threadIdx.x;

    if (tid < RB * FF) sidx[tid] = feats[b0 * FF + tid];
    __syncthreads();
    for (int e = tid; e < RB * FF * KK; e += NTHR) {
        int rf = e >> 4, k = e & 15;
        st[rf * SE + k] = v[(size_t)sidx[rf] * KK + k];
    }
    __syncthreads();

    float* PS3 = g_PS3 + (size_t)bg * TTP;
    float* PQ3 = g_PQ3 + (size_t)bg * TTP;

    for (int q = tid; q < PP; q += NTHR) {
        int d  = g_qdec[q];
        int a  = d & 255, b2 = d >> 8;

        float4 pr[RB][4];
        float  x2[RB];
        #pragma unroll
        for (int r = 0; r < RB; r++) {
            const float4* ea = (const float4*)&st[(r * FF + a) * SE];
            const float4* eb = (const float4*)&st[(r * FF + b2) * SE];
            float s2 = 0.f;
            #pragma unroll
            for (int j = 0; j < 4; j++) {
                float4 x = ea[j], y = eb[j], m;
                m.x = x.x*y.x; m.y = x.y*y.y; m.z = x.z*y.z; m.w = x.w*y.w;
                pr[r][j] = m;
                s2 += m.x + m.y + m.z + m.w;
            }
            x2[r] = s2;
        }

        g_PS2[bg * PPP + q] = x2[0] + x2[1] + x2[2] + x2[3];
        g_PQ2[bg * PPP + q] = x2[0]*x2[0] + x2[1]*x2[1] + x2[2]*x2[2] + x2[3]*x2[3];

        int c0   = b2 + 1;
        int base = (c0 * (c0 - 1) * (c0 - 2)) / 6;
        int inc  = (c0 * (c0 - 1)) / 2;
        for (int c = c0; c < FF; c++) {
            float vv[RB];
            #pragma unroll
            for (int r = 0; r < RB; r++) {
                const float4* ec = (const float4*)&st[(r * FF + c) * SE];
                float s = 0.f;
                #pragma unroll
                for (int j = 0; j < 4; j++) {
                    float4 p = pr[r][j], e = ec[j];
                    s += p.x*e.x + p.y*e.y + p.z*e.z + p.w*e.w;
                }
                vv[r] = s;
            }
            int col = base + q;
            PS3[col] = (vv[0] + vv[1]) + (vv[2] + vv[3]);
            PQ3[col] = (vv[0]*vv[0] + vv[1]*vv[1]) + (vv[2]*vv[2] + vv[3]*vv[3]);
            base += inc;
            inc  += c;
        }
    }
}

// ---------------------------------------------------------------------------
// Reduce: sum NBG partial slices into g_s/g_q (GSP-way split, few atomics)
// ---------------------------------------------------------------------------
__global__ __launch_bounds__(NTHR) void reduce_partials()
{
    const int t  = blockIdx.x * NTHR + threadIdx.x;
    const int g0 = blockIdx.y * (NBG / GSP);
    if (t < TT) {
        float s = 0.f, qq = 0.f;
        #pragma unroll 8
        for (int g = g0; g < g0 + NBG / GSP; g++) {
            s  += g_PS3[(size_t)g * TTP + t];
            qq += g_PQ3[(size_t)g * TTP + t];
        }
        atomicAdd(&g_s3[t], s);
        atomicAdd(&g_q3[t], qq);
    }
    if (t < PP) {
        float s = 0.f, qq = 0.f;
        #pragma unroll 8
        for (int g = g0; g < g0 + NBG / GSP; g++) {
            s  += g_PS2[g * PPP + t];
            qq += g_PQ2[g * PPP + t];
        }
        atomicAdd(&g_s2[t], s);
        atomicAdd(&g_q2[t], qq);
    }
}

// ---------------------------------------------------------------------------
// Finalize: sums -> affine coefficients c; accumulate Sum(o) into g_sumo
// ---------------------------------------------------------------------------
__global__ __launch_bounds__(NTHR) void finalize()
{
    const int i = blockIdx.x * NTHR + threadIdx.x;
    float osum = 0.f;
    if (i < TT) {
        float mean = g_s3[i] * (1.0f / BB);
        float var  = g_q3[i] * (1.0f / BB) - mean * mean;
        float inv  = rsqrtf(var + 1e-3f);
        float cc   = g_g3[i] * g_w3[i] * inv;
        g_c3[i] = cc;
        osum += g_b3p[i] * g_w3[i] - cc * mean;
    }
    if (i < PP) {
        float mean = g_s2[i] * (1.0f / BB);
        float var  = g_q2[i] * (1.0f / BB) - mean * mean;
        float inv  = rsqrtf(var + 1e-3f);
        float cc   = g_g2[i] * g_w2[i] * inv;
        g_c2[i] = cc;
        osum += g_b2p[i] * g_w2[i] - cc * mean;
    }
    #pragma unroll
    for (int o = 16; o; o >>= 1) osum += __shfl_down_sync(0xffffffffu, osum, o);
    __shared__ float red[8];
    if ((threadIdx.x & 31) == 0) red[threadIdx.x >> 5] = osum;
    __syncthreads();
    if (threadIdx.x == 0) {
        float s = 0.f;
        #pragma unroll
        for (int j = 0; j < 8; j++) s += red[j];
        atomicAdd(&g_sumo, s);
    }
}

// ---------------------------------------------------------------------------
// Pass F: recompute values, dot with c3/c2 (smem-staged), emit logits directly
// dynamic smem: sc3[TT] | sc2[PP] | tiles[RB*FF*SE]   (~52 KB)
// ---------------------------------------------------------------------------
__global__ __launch_bounds__(NTHR, 2) void pass_final(
    const int* __restrict__ feats, const float* __restrict__ w,
    const float* __restrict__ v, const float* __restrict__ bias,
    float* __restrict__ out)
{
    extern __shared__ float dsm[];
    float* sc3 = dsm;                    // TT floats
    float* sc2 = dsm + TT;               // PP floats
    float* st  = dsm + TT + PP;          // RB*FF*SE floats
    __shared__ int   sidx[RB * FF];
    __shared__ float slin[RB];
    __shared__ float wred[8][RB];

    const int bg  = blockIdx.x;
    const int b0  = bg * RB;
    const int tid = threadIdx.x;

    if (tid < RB * FF) sidx[tid] = feats[b0 * FF + tid];
    for (int i = tid; i < TT; i += NTHR) sc3[i] = g_c3[i];
    for (int i = tid; i < PP; i += NTHR) sc2[i] = g_c2[i];
    __syncthreads();
    for (int e = tid; e < RB * FF * KK; e += NTHR) {
        int rf = e >> 4, k = e & 15;
        st[rf * SE + k] = v[(size_t)sidx[rf] * KK + k];
    }
    if (tid < RB * 32) {                  // linear term: one warp per row
        int r = tid >> 5, lane = tid & 31;
        float s = 0.f;
        for (int f = lane; f < FF; f += 32) s += w[sidx[r * FF + f]];
        #pragma unroll
        for (int o = 16; o; o >>= 1) s += __shfl_down_sync(0xffffffffu, s, o);
        if (lane == 0) slin[r] = s;
    }
    __syncthreads();

    float acc[RB] = {0.f, 0.f, 0.f, 0.f};

    for (int q = tid; q < PP; q += NTHR) {
        int d  = g_qdec[q];
        int a  = d & 255, b2 = d >> 8;

        float4 pr[RB][4];
        float  x2[RB];
        #pragma unroll
        for (int r = 0; r < RB; r++) {
            const float4* ea = (const float4*)&st[(r * FF + a) * SE];
            const float4* eb = (const float4*)&st[(r * FF + b2) * SE];
            float s2 = 0.f;
            #pragma unroll
            for (int j = 0; j < 4; j++) {
                float4 x = ea[j], y = eb[j], m;
                m.x = x.x*y.x; m.y = x.y*y.y; m.z = x.z*y.z; m.w = x.w*y.w;
                pr[r][j] = m;
                s2 += m.x + m.y + m.z + m.w;
            }
            x2[r] = s2;
        }

        float c2v = sc2[q];
        #pragma unroll
        for (int r = 0; r < RB; r++) acc[r] += c2v * x2[r];

        int c0   = b2 + 1;
        int base = (c0 * (c0 - 1) * (c0 - 2)) / 6;
        int inc  = (c0 * (c0 - 1)) / 2;
        for (int c = c0; c < FF; c++) {
            float c3v = sc3[base + q];
            #pragma unroll
            for (int r = 0; r < RB; r++) {
                const float4* ec = (const float4*)&st[(r * FF + c) * SE];
                float s = 0.f;
                #pragma unroll
                for (int j = 0; j < 4; j++) {
                    float4 p = pr[r][j], e = ec[j];
                    s += p.x*e.x + p.y*e.y + p.z*e.z + p.w*e.w;
                }
                acc[r] += c3v * s;
            }
            base += inc;
            inc  += c;
        }
    }

    // CTA reduction of the RB accumulators
    #pragma unroll
    for (int j = 0; j < RB; j++) {
        float s = acc[j];
        #pragma unroll
        for (int o = 16; o; o >>= 1) s += __shfl_down_sync(0xffffffffu, s, o);
        if ((tid & 31) == 0) wred[tid >> 5][j] = s;
    }
    __syncthreads();
    if (tid < RB) {
        float s = 0.f;
        #pragma unroll
        for (int wp = 0; wp < 8; wp++) s += wred[wp][tid];
        out[b0 + tid] = s + slin[tid] + bias[0] + g_sumo;
    }
}

// ---------------------------------------------------------------------------
extern "C" void kernel_launch(void* const* d_in, const int* in_sizes, int n_in,
                              void* d_out, int out_size)
{
    const int*   feats  = (const int*)  d_in[0];
    const float* w      = (const float*)d_in[1];
    const float* v      = (const float*)d_in[2];
    const float* bias   = (const float*)d_in[3];
    const float* gamma2 = (const float*)d_in[4];
    const float* beta2  = (const float*)d_in[5];
    const float* gw2    = (const float*)d_in[6];
    const float* gamma3 = (const float*)d_in[7];
    const float* beta3  = (const float*)d_in[8];
    const float* gw3    = (const float*)d_in[9];
    const int*   rows   = (const int*)  d_in[10];
    const int*   cols   = (const int*)  d_in[11];
    const int*   i1     = (const int*)  d_in[12];
    const int*   i2     = (const int*)  d_in[13];
    const int*   i3     = (const int*)  d_in[14];
    float* out = (float*)d_out;

    const int dyn_smem = (TT + PP + RB * FF * SE) * (int)sizeof(float);  // ~52 KB
    cudaFuncSetAttribute(pass_final,
                         cudaFuncAttributeMaxDynamicSharedMemorySize, dyn_smem);

    pack_tri<<<TTP / NTHR, NTHR>>>(i1, i2, i3, rows, cols,
                                   gamma2, beta2, gw2, gamma3, beta3, gw3);
    pass_stats<<<NBG, NTHR>>>(feats, v);
    reduce_partials<<<dim3(TTP / NTHR, GSP), NTHR>>>();
    finalize<<<TTP / NTHR, NTHR>>>();
    pass_final<<<NBG, NTHR, dyn_smem>>>(feats, w, v, bias, out);
}

// round 11
// speedup vs baseline: 1.3652x; 1.3652x over previous
#include <cuda_runtime.h>
#include <cuda_fp16.h>

#define BB   1024
#define FF   39
#define KK   16
#define PP   741
#define PPP  768                      // padded pair stride
#define TT   9139
#define TTP  9216                     // padded triple stride (36*256)
#define SE   20                       // embedding row stride (floats)
#define NTHR 256
#define BSPLIT 16                     // batch split for stats
#define TSPLIT 4                      // T split for final reduce
#define TCHUNK (TTP / TSPLIT)         // 2304
#define SCALE  65536.0f               // exact 2^16 scaling for fp16 storage

// ---- device-global scratch (no allocations allowed; zero-init at load,
//      padding regions are never written so they stay 0) ----
__device__ __align__(16) float  g_L2[BB * PPP];           // ~3.1 MB fp32
__device__ __align__(16) __half g_L3h[(size_t)BB * TTP];  // ~18.9 MB fp16 (x * 2^16)
__device__ float g_lin[BB];
__device__ __align__(16) float g_c2[PPP];    // pad stays 0
__device__ __align__(16) float g_c3[TTP];    // pad stays 0 (1/2^16 folded in)
__device__ float g_ps3[BSPLIT][TTP], g_pq3[BSPLIT][TTP];  // per-split partials
__device__ float g_ps2[BSPLIT][PPP], g_pq2[BSPLIT][PPP];
__device__ int   g_qdec[PP];                 // a | (b2<<8), canonical pair order
__device__ float g_g2[PP], g_b2p[PP], g_w2[PP];   // BN params permuted canonical
__device__ float g_g3[TT], g_b3p[TT], g_w3[TT];
__device__ float g_sumo;
__device__ float g_facc[BB];

// ---------------------------------------------------------------------------
// Kernel 0: canonical orderings + permuted BN params; zero atomic targets
//   pair  (a,b2):   q  = b2(b2-1)/2 + a      (b2-major)
//   triple(a,b2,c): tc = C(c,3) + q
// ---------------------------------------------------------------------------
__global__ void pack_tri(const int* __restrict__ i1, const int* __restrict__ i2,
                         const int* __restrict__ i3,
                         const int* __restrict__ rows, const int* __restrict__ cols,
                         const float* __restrict__ gamma2, const float* __restrict__ beta2,
                         const float* __restrict__ gw2,
                         const float* __restrict__ gamma3, const float* __restrict__ beta3,
                         const float* __restrict__ gw3) {
    int t = blockIdx.x * blockDim.x + threadIdx.x;
    if (t < TT) {
        int a = i1[t], b2 = i2[t], c = i3[t];
        int tc = (c * (c - 1) * (c - 2)) / 6 + (b2 * (b2 - 1)) / 2 + a;
        g_g3[tc]  = gamma3[t];
        g_b3p[tc] = beta3[t];
        g_w3[tc]  = gw3[t];
    }
    if (t < PP) {
        int r = rows[t], cl = cols[t];            // r > cl
        int q = (r * (r - 1)) / 2 + cl;
        g_qdec[q] = cl | (r << 8);
        g_g2[q]  = gamma2[t];
        g_b2p[q] = beta2[t];
        g_w2[q]  = gw2[t];
    }
    if (t < BB) g_facc[t] = 0.f;
    if (t == 0) g_sumo = 0.f;
}

// ---------------------------------------------------------------------------
// Kernel A: per-batch-row gather + level2 (fp32) + level3 (fp16, x*2^16)
// (round-8 structure: 1024 CTAs, register pair products, broadcast Ec loads)
// ---------------------------------------------------------------------------
__global__ __launch_bounds__(NTHR) void compute_levels(
    const int*   __restrict__ feats,
    const float* __restrict__ w,
    const float* __restrict__ v)
{
    __shared__ float sxv[FF * SE];
    __shared__ int   sidx[FF];

    const int b   = blockIdx.x;
    const int tid = threadIdx.x;

    if (tid < FF) sidx[tid] = feats[b * FF + tid];
    __syncthreads();

    for (int e = tid; e < FF * KK; e += NTHR) {
        int f = e >> 4, k = e & 15;
        sxv[f * SE + k] = v[(size_t)sidx[f] * KK + k];
    }
    if (tid < 32) {
        float s = 0.f;
        for (int f = tid; f < FF; f += 32) s += w[sidx[f]];
        #pragma unroll
        for (int o = 16; o; o >>= 1) s += __shfl_down_sync(0xffffffffu, s, o);
        if (tid == 0) g_lin[b] = s;
    }
    __syncthreads();

    __half* dst = g_L3h + (size_t)b * TTP;

    for (int q = tid; q < PP; q += NTHR) {
        int d  = __ldg(&g_qdec[q]);
        int a  = d & 255, b2 = d >> 8;
        const float4* ea = (const float4*)&sxv[a * SE];
        const float4* eb = (const float4*)&sxv[b2 * SE];

        float4 p0, p1, p2, p3;
        {
            float4 x, y;
            x = ea[0]; y = eb[0];
            p0.x = x.x*y.x; p0.y = x.y*y.y; p0.z = x.z*y.z; p0.w = x.w*y.w;
            x = ea[1]; y = eb[1];
            p1.x = x.x*y.x; p1.y = x.y*y.y; p1.z = x.z*y.z; p1.w = x.w*y.w;
            x = ea[2]; y = eb[2];
            p2.x = x.x*y.x; p2.y = x.y*y.y; p2.z = x.z*y.z; p2.w = x.w*y.w;
            x = ea[3]; y = eb[3];
            p3.x = x.x*y.x; p3.y = x.y*y.y; p3.z = x.z*y.z; p3.w = x.w*y.w;
        }
        g_L2[b * PPP + q] = (p0.x+p0.y+p0.z+p0.w) + (p1.x+p1.y+p1.z+p1.w)
                          + (p2.x+p2.y+p2.z+p2.w) + (p3.x+p3.y+p3.z+p3.w);

        int c0   = b2 + 1;
        int base = (c0 * (c0 - 1) * (c0 - 2)) / 6;
        int inc  = (c0 * (c0 - 1)) / 2;
        for (int c = c0; c < FF; c++) {
            const float4* ec = (const float4*)&sxv[c * SE];   // broadcast
            float4 e0 = ec[0], e1 = ec[1], e2 = ec[2], e3 = ec[3];
            float s0 = p0.x*e0.x + p0.y*e0.y + p0.z*e0.z + p0.w*e0.w;
            float s1 = p1.x*e1.x + p1.y*e1.y + p1.z*e1.z + p1.w*e1.w;
            float s2 = p2.x*e2.x + p2.y*e2.y + p2.z*e2.z + p2.w*e2.w;
            float s3 = p3.x*e3.x + p3.y*e3.y + p3.z*e3.z + p3.w*e3.w;
            dst[base + q] = __float2half_rn(((s0 + s1) + (s2 + s3)) * SCALE);
            base += inc;
            inc  += c;
        }
    }
}

// ---------------------------------------------------------------------------
// Kernel B: fused batch-split column stats (L3 fp16 + L2 fp32), NO atomics.
// grid (36+3, BSPLIT). Each tx owns 8 consecutive columns; 64 rows per split.
// ---------------------------------------------------------------------------
__global__ __launch_bounds__(NTHR) void stats_acc()
{
    __shared__ float shs[8][NTHR], shq[8][NTHR];
    const int tx = threadIdx.x & 31;
    const int ty = threadIdx.x >> 5;
    const int split = blockIdx.y;
    const int b0 = split * (BB / BSPLIT);     // 64 rows

    float s[8], q[8];
    #pragma unroll
    for (int e = 0; e < 8; e++) { s[e] = 0.f; q[e] = 0.f; }

    if (blockIdx.x < TTP / 256) {
        const int t0 = blockIdx.x * 256 + tx * 8;
        for (int i = ty; i < BB / BSPLIT; i += 8) {
            uint4 h = *(const uint4*)(g_L3h + (size_t)(b0 + i) * TTP + t0);
            const __half2* hp = (const __half2*)&h;
            #pragma unroll
            for (int e = 0; e < 4; e++) {
                float2 f = __half22float2(hp[e]);
                s[2*e]   += f.x; q[2*e]   += f.x * f.x;
                s[2*e+1] += f.y; q[2*e+1] += f.y * f.y;
            }
        }
        #pragma unroll
        for (int e = 0; e < 8; e++) { shs[ty][tx*8+e] = s[e]; shq[ty][tx*8+e] = q[e]; }
        __syncthreads();
        int col = threadIdx.x;
        float S = 0.f, Q = 0.f;
        #pragma unroll
        for (int j = 0; j < 8; j++) { S += shs[j][col]; Q += shq[j][col]; }
        g_ps3[split][blockIdx.x * 256 + col] = S;
        g_pq3[split][blockIdx.x * 256 + col] = Q;
    } else {
        const int p0 = (blockIdx.x - TTP / 256) * 256 + tx * 8;
        for (int i = ty; i < BB / BSPLIT; i += 8) {
            const float4* xp = (const float4*)(g_L2 + (b0 + i) * PPP + p0);
            float4 x = xp[0], y = xp[1];
            s[0]+=x.x; q[0]+=x.x*x.x;  s[1]+=x.y; q[1]+=x.y*x.y;
            s[2]+=x.z; q[2]+=x.z*x.z;  s[3]+=x.w; q[3]+=x.w*x.w;
            s[4]+=y.x; q[4]+=y.x*y.x;  s[5]+=y.y; q[5]+=y.y*y.y;
            s[6]+=y.z; q[6]+=y.z*y.z;  s[7]+=y.w; q[7]+=y.w*y.w;
        }
        #pragma unroll
        for (int e = 0; e < 8; e++) { shs[ty][tx*8+e] = s[e]; shq[ty][tx*8+e] = q[e]; }
        __syncthreads();
        int col = threadIdx.x;
        float S = 0.f, Q = 0.f;
        #pragma unroll
        for (int j = 0; j < 8; j++) { S += shs[j][col]; Q += shq[j][col]; }
        g_ps2[split][(blockIdx.x - TTP / 256) * 256 + col] = S;
        g_pq2[split][(blockIdx.x - TTP / 256) * 256 + col] = Q;
    }
}

// ---------------------------------------------------------------------------
// Kernel C: sum partials -> affine coefficients; accumulate Sum(o)
// (scale handling: stats are of SCALED values; c3 carries 1/SCALE)
// ---------------------------------------------------------------------------
__global__ __launch_bounds__(NTHR) void finalize()
{
    const int t = blockIdx.x * NTHR + threadIdx.x;
    float osum = 0.f;
    {
        float S = 0.f, Q = 0.f;
        #pragma unroll
        for (int sp = 0; sp < BSPLIT; sp++) { S += g_ps3[sp][t]; Q += g_pq3[sp][t]; }
        if (t < TT) {
            float mean_s = S * (1.0f / BB);                       // scaled mean
            float var_s  = Q * (1.0f / BB) - mean_s * mean_s;     // scaled^2 var
            float inv    = rsqrtf(var_s * (1.0f / (SCALE * SCALE)) + 1e-3f);
            float c_true = g_g3[t] * g_w3[t] * inv;
            float c3p    = c_true * (1.0f / SCALE);
            g_c3[t] = c3p;
            osum += g_b3p[t] * g_w3[t] - c3p * mean_s;            // c_true*mean_true
        }
    }
    if (t < PP) {
        float S = 0.f, Q = 0.f;
        #pragma unroll
        for (int sp = 0; sp < BSPLIT; sp++) { S += g_ps2[sp][t]; Q += g_pq2[sp][t]; }
        float mean = S * (1.0f / BB);
        float var  = Q * (1.0f / BB) - mean * mean;
        float inv  = rsqrtf(var + 1e-3f);
        float cc   = g_g2[t] * g_w2[t] * inv;
        g_c2[t] = cc;
        osum += g_b2p[t] * g_w2[t] - cc * mean;
    }
    #pragma unroll
    for (int o = 16; o; o >>= 1) osum += __shfl_down_sync(0xffffffffu, osum, o);
    __shared__ float red[8];
    if ((threadIdx.x & 31) == 0) red[threadIdx.x >> 5] = osum;
    __syncthreads();
    if (threadIdx.x == 0) {
        float s = 0.f;
        #pragma unroll
        for (int j = 0; j < 8; j++) s += red[j];
        atomicAdd(&g_sumo, s);
    }
}

// ---------------------------------------------------------------------------
// Kernel D: weighted reductions. 8 b-rows per CTA, T split 4-way.
// L3 read as half8 (uint4); pad columns: c3=0 and L3h=0 -> safe.
// ---------------------------------------------------------------------------
__global__ __launch_bounds__(NTHR) void final_reduce()
{
    const int b0  = blockIdx.x * 8;
    const int tid = threadIdx.x;
    const int tlo = blockIdx.y * TCHUNK;
    const int thi = tlo + TCHUNK;
    float acc[8] = {0.f, 0.f, 0.f, 0.f, 0.f, 0.f, 0.f, 0.f};

    for (int t = tlo + tid * 8; t < thi; t += NTHR * 8) {
        float4 c0 = *(const float4*)&g_c3[t];
        float4 c1 = *(const float4*)&g_c3[t + 4];
        const __half* base = g_L3h + (size_t)b0 * TTP + t;
        #pragma unroll
        for (int j = 0; j < 8; j++) {
            uint4 h = *(const uint4*)(base + (size_t)j * TTP);
            const __half2* hp = (const __half2*)&h;
            float2 f0 = __half22float2(hp[0]), f1 = __half22float2(hp[1]);
            float2 f2 = __half22float2(hp[2]), f3 = __half22float2(hp[3]);
            acc[j] += c0.x*f0.x + c0.y*f0.y + c0.z*f1.x + c0.w*f1.y
                    + c1.x*f2.x + c1.y*f2.y + c1.z*f3.x + c1.w*f3.y;
        }
    }
    if (blockIdx.y == 0) {
        for (int p = tid * 4; p < PPP; p += NTHR * 4) {
            float4 c = *(const float4*)&g_c2[p];
            const float* base = g_L2 + b0 * PPP + p;
            #pragma unroll
            for (int j = 0; j < 8; j++) {
                float4 x = *(const float4*)(base + j * PPP);
                acc[j] += c.x * x.x + c.y * x.y + c.z * x.z + c.w * x.w;
            }
        }
    }

    __shared__ float red[8][8];   // [warp][j]
    #pragma unroll
    for (int j = 0; j < 8; j++) {
        float vsum = acc[j];
        #pragma unroll
        for (int o = 16; o; o >>= 1) vsum += __shfl_down_sync(0xffffffffu, vsum, o);
        if ((tid & 31) == 0) red[tid >> 5][j] = vsum;
    }
    __syncthreads();
    if (tid < 8) {
        float s = 0.f;
        #pragma unroll
        for (int wp = 0; wp < 8; wp++) s += red[wp][tid];
        atomicAdd(&g_facc[b0 + tid], s);
    }
}

// ---------------------------------------------------------------------------
// Kernel E: epilogue -> logits
// ---------------------------------------------------------------------------
__global__ void epilogue(const float* __restrict__ bias, float* __restrict__ out)
{
    int b = blockIdx.x * blockDim.x + threadIdx.x;
    if (b < BB) out[b] = g_facc[b] + g_lin[b] + bias[0] + g_sumo;
}

// ---------------------------------------------------------------------------
extern "C" void kernel_launch(void* const* d_in, const int* in_sizes, int n_in,
                              void* d_out, int out_size)
{
    const int*   feats  = (const int*)  d_in[0];
    const float* w      = (const float*)d_in[1];
    const float* v      = (const float*)d_in[2];
    const float* bias   = (const float*)d_in[3];
    const float* gamma2 = (const float*)d_in[4];
    const float* beta2  = (const float*)d_in[5];
    const float* gw2    = (const float*)d_in[6];
    const float* gamma3 = (const float*)d_in[7];
    const float* beta3  = (const float*)d_in[8];
    const float* gw3    = (const float*)d_in[9];
    const int*   rows   = (const int*)  d_in[10];
    const int*   cols   = (const int*)  d_in[11];
    const int*   i1     = (const int*)  d_in[12];
    const int*   i2     = (const int*)  d_in[13];
    const int*   i3     = (const int*)  d_in[14];
    float* out = (float*)d_out;

    pack_tri<<<TTP / NTHR, NTHR>>>(i1, i2, i3, rows, cols,
                                   gamma2, beta2, gw2, gamma3, beta3, gw3);
    compute_levels<<<BB, NTHR>>>(feats, w, v);
    stats_acc<<<dim3(TTP / 256 + PPP / 256, BSPLIT), NTHR>>>();
    finalize<<<TTP / NTHR, NTHR>>>();
    final_reduce<<<dim3(BB / 8, TSPLIT), NTHR>>>();
    epilogue<<<BB / NTHR, NTHR>>>(bias, out);
}